// round 4
// baseline (speedup 1.0000x reference)
#include <cuda_runtime.h>
#include <cuda_bf16.h>

#define BATCH 4
#define S 1024
#define D 1024
#define H 16
#define DK 64

// ---------------------------------------------------------------------------
// scratch (allocation-free: __device__ globals)
// split bf16: value ~= hi + lo
// ---------------------------------------------------------------------------
__device__ __nv_bfloat16 g_q_hi[BATCH * S * D];
__device__ __nv_bfloat16 g_q_lo[BATCH * S * D];
__device__ __nv_bfloat16 g_k_hi[BATCH * S * D];
__device__ __nv_bfloat16 g_k_lo[BATCH * S * D];
__device__ __nv_bfloat16 g_xq_hi[BATCH * S * D];
__device__ __nv_bfloat16 g_xq_lo[BATCH * S * D];
__device__ __nv_bfloat16 g_xk_hi[BATCH * S * D];
__device__ __nv_bfloat16 g_xk_lo[BATCH * S * D];
__device__ __nv_bfloat16 g_wq_hi[D * D];
__device__ __nv_bfloat16 g_wq_lo[D * D];
__device__ __nv_bfloat16 g_wk_hi[D * D];
__device__ __nv_bfloat16 g_wk_lo[D * D];
__device__ float g_asco[BATCH * H * S];

// ---------------------------------------------------------------------------
// helpers
// ---------------------------------------------------------------------------
__device__ __forceinline__ unsigned sm_u32(const void* p) {
    return (unsigned)__cvta_generic_to_shared(p);
}

__device__ __forceinline__ void ldsm4(unsigned r[4], unsigned addr) {
    asm volatile("ldmatrix.sync.aligned.m8n8.x4.shared.b16 {%0,%1,%2,%3}, [%4];"
                 : "=r"(r[0]), "=r"(r[1]), "=r"(r[2]), "=r"(r[3])
                 : "r"(addr));
}

__device__ __forceinline__ void mma16816(float* c, const unsigned* a, const unsigned* b) {
    asm volatile(
        "mma.sync.aligned.m16n8k16.row.col.f32.bf16.bf16.f32 "
        "{%0,%1,%2,%3}, {%4,%5,%6,%7}, {%8,%9}, {%0,%1,%2,%3};"
        : "+f"(c[0]), "+f"(c[1]), "+f"(c[2]), "+f"(c[3])
        : "r"(a[0]), "r"(a[1]), "r"(a[2]), "r"(a[3]), "r"(b[0]), "r"(b[1]));
}

__device__ __forceinline__ void split_pack(float x, float y, unsigned& hi, unsigned& lo) {
    __nv_bfloat162 h, l;
    h.x = __float2bfloat16(x);
    h.y = __float2bfloat16(y);
    l.x = __float2bfloat16(x - __bfloat162float(h.x));
    l.y = __float2bfloat16(y - __bfloat162float(h.y));
    hi = *reinterpret_cast<unsigned*>(&h);
    lo = *reinterpret_cast<unsigned*>(&l);
}

__device__ __forceinline__ void cpa16(unsigned dst, const void* src) {
    asm volatile("cp.async.cg.shared.global [%0], [%1], 16;" :: "r"(dst), "l"(src));
}
#define CP_COMMIT() asm volatile("cp.async.commit_group;")
#define CP_WAIT(N)  asm volatile("cp.async.wait_group %0;" :: "n"(N))
#define PREF_L2(p)  asm volatile("prefetch.global.L2 [%0];" :: "l"(p))

// ---------------------------------------------------------------------------
// Kernel 0: fp32 -> split bf16 (hi/lo) conversion, one pass.
// ---------------------------------------------------------------------------
__global__ __launch_bounds__(256) void convert_kernel(
    const float* __restrict__ src, __nv_bfloat16* __restrict__ hi,
    __nv_bfloat16* __restrict__ lo, int n4)
{
    int i = blockIdx.x * blockDim.x + threadIdx.x;
    if (i < n4) {
        float4 v = ((const float4*)src)[i];
        unsigned h0, l0, h1, l1;
        split_pack(v.x, v.y, h0, l0);
        split_pack(v.z, v.w, h1, l1);
        ((uint2*)hi)[i] = make_uint2(h0, h1);
        ((uint2*)lo)[i] = make_uint2(l0, l1);
    }
}

// ---------------------------------------------------------------------------
// Kernel 1: C = X @ W^T + bias (pure bf16 pipeline, cp.async double-buffered)
// 128x128 CTA tile, BK=32. smem/stage: 4 arrays x 128 rows x 80B = 40KB,
// 2 stages = 80KB. 3-term split-bf16 mma.
// ---------------------------------------------------------------------------
#define PJ_AHI 0
#define PJ_ALO 10240
#define PJ_BHI 20480
#define PJ_BLO 30720
#define PJ_BUF 40960

__device__ __forceinline__ void pj_load_stage(
    unsigned sdst, int tid,
    const __nv_bfloat16* __restrict__ Xhi, const __nv_bfloat16* __restrict__ Xlo,
    const __nv_bfloat16* __restrict__ Whi, const __nv_bfloat16* __restrict__ Wlo,
    int m0, int n0, int k0)
{
#pragma unroll
    for (int l = 0; l < 8; l++) {
        int rem = tid + (l & 1) * 256;     // 0..511
        int row = rem >> 2, ch = rem & 3;
        unsigned dst = sdst + (l >> 1) * 10240 + row * 80 + ch * 16;
        const __nv_bfloat16* src;
        switch (l >> 1) {
            case 0: src = Xhi + (size_t)(m0 + row) * D + k0 + ch * 8; break;
            case 1: src = Xlo + (size_t)(m0 + row) * D + k0 + ch * 8; break;
            case 2: src = Whi + (size_t)(n0 + row) * D + k0 + ch * 8; break;
            default: src = Wlo + (size_t)(n0 + row) * D + k0 + ch * 8; break;
        }
        cpa16(dst, src);
    }
}

__global__ void __launch_bounds__(256, 2) proj_kernel(
    const __nv_bfloat16* __restrict__ Xhi, const __nv_bfloat16* __restrict__ Xlo,
    const __nv_bfloat16* __restrict__ Whi, const __nv_bfloat16* __restrict__ Wlo,
    const float* __restrict__ bias,
    __nv_bfloat16* __restrict__ Chi, __nv_bfloat16* __restrict__ Clo)
{
    extern __shared__ char smem_raw[];
    const int tid = threadIdx.x;
    const int lane = tid & 31;
    const int wid = tid >> 5;
    const int wm = wid & 3;
    const int wn = wid >> 2;
    const int m0 = blockIdx.x * 128;
    const int n0 = blockIdx.y * 128;
    const unsigned sbase = sm_u32(smem_raw);

    float acc[2][8][4];
#pragma unroll
    for (int mt = 0; mt < 2; mt++)
#pragma unroll
        for (int nt = 0; nt < 8; nt++)
#pragma unroll
            for (int i = 0; i < 4; i++) acc[mt][nt][i] = 0.f;

    pj_load_stage(sbase, tid, Xhi, Xlo, Whi, Wlo, m0, n0, 0);
    CP_COMMIT();

    for (int c = 0; c < 32; c++) {
        if (c < 31) {
            pj_load_stage(sbase + ((c + 1) & 1) * PJ_BUF, tid,
                          Xhi, Xlo, Whi, Wlo, m0, n0, (c + 1) * 32);
            CP_COMMIT();
            CP_WAIT(1);
        } else {
            CP_WAIT(0);
        }
        __syncthreads();

        const unsigned base = sbase + (c & 1) * PJ_BUF;
#pragma unroll
        for (int kk = 0; kk < 2; kk++) {
            unsigned ahi[2][4], alo[2][4];
#pragma unroll
            for (int mt = 0; mt < 2; mt++) {
                unsigned rbytes = (unsigned)(wm * 32 + mt * 16 + (lane & 7) + ((lane >> 3) & 1) * 8) * 80
                                + ((lane >> 4) & 1) * 16 + kk * 32;
                ldsm4(ahi[mt], base + PJ_AHI + rbytes);
                ldsm4(alo[mt], base + PJ_ALO + rbytes);
            }
#pragma unroll
            for (int nt2 = 0; nt2 < 4; nt2++) {
                unsigned rbytes = (unsigned)(wn * 64 + nt2 * 16 + (lane & 7) + ((lane >> 4) & 1) * 8) * 80
                                + ((lane >> 3) & 1) * 16 + kk * 32;
                unsigned bhi[4], blo[4];
                ldsm4(bhi, base + PJ_BHI + rbytes);
                ldsm4(blo, base + PJ_BLO + rbytes);
#pragma unroll
                for (int mt = 0; mt < 2; mt++) {
                    mma16816(acc[mt][nt2 * 2],     ahi[mt], bhi);
                    mma16816(acc[mt][nt2 * 2 + 1], ahi[mt], bhi + 2);
                    mma16816(acc[mt][nt2 * 2],     ahi[mt], blo);
                    mma16816(acc[mt][nt2 * 2 + 1], ahi[mt], blo + 2);
                    mma16816(acc[mt][nt2 * 2],     alo[mt], bhi);
                    mma16816(acc[mt][nt2 * 2 + 1], alo[mt], bhi + 2);
                }
            }
        }
        __syncthreads();   // all consumers done before next issue overwrites
    }

    // ---- epilogue: bias add, split to hi/lo bf16, store ----
    const int q = lane >> 2, tig = lane & 3;
#pragma unroll
    for (int mt = 0; mt < 2; mt++) {
#pragma unroll
        for (int nt = 0; nt < 8; nt++) {
            int col = n0 + wn * 64 + nt * 8 + tig * 2;
            float2 bb = *(const float2*)(bias + col);
            int row = m0 + wm * 32 + mt * 16 + q;
            unsigned hi, lo;
            split_pack(acc[mt][nt][0] + bb.x, acc[mt][nt][1] + bb.y, hi, lo);
            *reinterpret_cast<unsigned*>(&Chi[(size_t)row * D + col]) = hi;
            *reinterpret_cast<unsigned*>(&Clo[(size_t)row * D + col]) = lo;
            split_pack(acc[mt][nt][2] + bb.x, acc[mt][nt][3] + bb.y, hi, lo);
            *reinterpret_cast<unsigned*>(&Chi[(size_t)(row + 8) * D + col]) = hi;
            *reinterpret_cast<unsigned*>(&Clo[(size_t)(row + 8) * D + col]) = lo;
        }
    }
}

// ---------------------------------------------------------------------------
// Kernel 2: aspect path.
// ---------------------------------------------------------------------------
__global__ __launch_bounds__(256) void aspect_kernel(
    const float* __restrict__ aspect, const float* __restrict__ Wd, const float* __restrict__ bd,
    const float* __restrict__ wm, const float* __restrict__ bm)
{
    const int bh = blockIdx.x;
    const int b = bh >> 4;
    const int h = bh & 15;
    const int tid = threadIdx.x;

    __shared__ float asp_s[64];
    __shared__ float aw_s[64];

    {
        int e = tid >> 2, p = tid & 3;
        const float* av = aspect + (size_t)b * D + p * 256;
        const float* wv = Wd + (size_t)e * D + p * 256;
        float sum = 0.f;
#pragma unroll 4
        for (int d = 0; d < 256; d += 4) {
            float4 a = *(const float4*)(av + d);
            float4 w = *(const float4*)(wv + d);
            sum += a.x * w.x + a.y * w.y + a.z * w.z + a.w * w.w;
        }
        sum += __shfl_xor_sync(0xffffffffu, sum, 1, 4);
        sum += __shfl_xor_sync(0xffffffffu, sum, 2, 4);
        if (p == 0) asp_s[e] = sum + bd[e];
    }
    __syncthreads();
    if (tid < 64) {
        float s = 0.f;
        const float* w = wm + (size_t)h * DK * DK + tid;
#pragma unroll 8
        for (int c = 0; c < 64; c++) s += asp_s[c] * w[c * 64];
        aw_s[tid] = s;
    }
    __syncthreads();
    const float bias = bm[0];
    for (int j = tid; j < S; j += 256) {
        const __nv_bfloat162* kh =
            reinterpret_cast<const __nv_bfloat162*>(g_k_hi + ((size_t)b * S + j) * D + h * DK);
        const __nv_bfloat162* kl =
            reinterpret_cast<const __nv_bfloat162*>(g_k_lo + ((size_t)b * S + j) * D + h * DK);
        float s = 0.f;
#pragma unroll
        for (int d2 = 0; d2 < 32; d2++) {
            float2 a = __bfloat1622float2(kh[d2]);
            float2 c = __bfloat1622float2(kl[d2]);
            s += aw_s[2 * d2] * (a.x + c.x) + aw_s[2 * d2 + 1] * (a.y + c.y);
        }
        float x = s + bias;
        float t = 1.f - 2.f / (__expf(2.f * x) + 1.f);
        g_asco[(size_t)bh * S + j] = t;
    }
}

// ---------------------------------------------------------------------------
// Kernel 3: fused scores + softmax. cp.async K loads + L2 prefetch of the
// epilogue's short/mask regions and K chunk 1.
// ---------------------------------------------------------------------------
#define SC_SQHI 0
#define SC_SQLO 4608
#define SC_ASCS 9216
#define SC_REDM 13312
#define SC_REDS 15488
#define SC_REDM2 17664
#define SC_REDS2 17792
#define SC_SKHI 17920
#define SC_SKLO 99840
#define SC_TOTAL 181760

__global__ void __launch_bounds__(512, 1) scores_kernel(
    const float* __restrict__ shortp, const int* __restrict__ mask, float* __restrict__ out)
{
    extern __shared__ char smem_raw[];
    const int b = blockIdx.z;
    const int h = blockIdx.y;
    const int m0 = blockIdx.x * 32;
    const int bh = b * H + h;
    const int tid = threadIdx.x;
    const int lane = tid & 31;
    const int wid = tid >> 5;
    const unsigned sbase = sm_u32(smem_raw);

    // ---- Q tile (32 rows x 64 dk, hi+lo) ----
    {
        int row = tid >> 4, g = tid & 15;
        size_t goff = ((size_t)(b * S) + m0 + row) * D + h * DK + g * 4;
        *(uint2*)(smem_raw + SC_SQHI + row * 144 + g * 8) = *(const uint2*)(g_q_hi + goff);
        *(uint2*)(smem_raw + SC_SQLO + row * 144 + g * 8) = *(const uint2*)(g_q_lo + goff);
    }
    // ---- aspect scores ----
    ((float2*)(smem_raw + SC_ASCS))[tid] = *(const float2*)(g_asco + (size_t)bh * S + tid * 2);

    // ---- issue K chunk 0 (cp.async) ----
#pragma unroll
    for (int l = 0; l < 8; l++) {
        int f = tid + l * 512;
        int row = f >> 2, g = f & 3;
        size_t goff = ((size_t)(b * S) + row) * D + h * DK + g * 8;
        cpa16(sbase + SC_SKHI + row * 80 + g * 16, g_k_hi + goff);
        cpa16(sbase + SC_SKLO + row * 80 + g * 16, g_k_lo + goff);
    }
    CP_COMMIT();

    // ---- prefetch to L2: short, mask, K chunk 1 (overlap with chunk0 land) ----
    {
        const char* shbase = (const char*)(shortp + ((size_t)bh * S + m0) * S);
        const char* mkbase = (const char*)(mask + ((size_t)b * S + m0) * S);
#pragma unroll
        for (int l = 0; l < 2; l++) {
            int line = tid + l * 512;          // 1024 lines x 128B = 128KB each
            PREF_L2(shbase + (size_t)line * 128);
            PREF_L2(mkbase + (size_t)line * 128);
        }
#pragma unroll
        for (int l = 0; l < 2; l++) {
            int row = tid + l * 512;
            size_t goff = ((size_t)(b * S) + row) * D + h * DK + 32;
            PREF_L2((const char*)(g_k_hi + goff));
            PREF_L2((const char*)(g_k_lo + goff));
        }
    }

    float acc[2][8][4];
#pragma unroll
    for (int mt = 0; mt < 2; mt++)
#pragma unroll
        for (int nt = 0; nt < 8; nt++)
#pragma unroll
            for (int i = 0; i < 4; i++) acc[mt][nt][i] = 0.f;

    for (int chunk = 0; chunk < 2; chunk++) {
        if (chunk) {
            __syncthreads();   // chunk0 consumers done before overwrite
#pragma unroll
            for (int l = 0; l < 8; l++) {
                int f = tid + l * 512;
                int row = f >> 2, g = f & 3;
                size_t goff = ((size_t)(b * S) + row) * D + h * DK + 32 + g * 8;
                cpa16(sbase + SC_SKHI + row * 80 + g * 16, g_k_hi + goff);
                cpa16(sbase + SC_SKLO + row * 80 + g * 16, g_k_lo + goff);
            }
            CP_COMMIT();
        }
        CP_WAIT(0);
        __syncthreads();

#pragma unroll
        for (int kk2 = 0; kk2 < 2; kk2++) {
            const int kglob = chunk * 2 + kk2;
            unsigned ahi[2][4], alo[2][4];
#pragma unroll
            for (int mt = 0; mt < 2; mt++) {
                unsigned rbytes = (unsigned)(mt * 16 + (lane & 7) + ((lane >> 3) & 1) * 8) * 144
                                + ((lane >> 4) & 1) * 16 + kglob * 32;
                ldsm4(ahi[mt], sbase + SC_SQHI + rbytes);
                ldsm4(alo[mt], sbase + SC_SQLO + rbytes);
            }
#pragma unroll
            for (int nt2 = 0; nt2 < 4; nt2++) {
                unsigned rbytes = (unsigned)(wid * 64 + nt2 * 16 + (lane & 7) + ((lane >> 4) & 1) * 8) * 80
                                + ((lane >> 3) & 1) * 16 + kk2 * 32;
                unsigned bhi[4], blo[4];
                ldsm4(bhi, sbase + SC_SKHI + rbytes);
                ldsm4(blo, sbase + SC_SKLO + rbytes);
#pragma unroll
                for (int mt = 0; mt < 2; mt++) {
                    mma16816(acc[mt][nt2 * 2],     ahi[mt], bhi);
                    mma16816(acc[mt][nt2 * 2 + 1], ahi[mt], bhi + 2);
                    mma16816(acc[mt][nt2 * 2],     ahi[mt], blo);
                    mma16816(acc[mt][nt2 * 2 + 1], ahi[mt], blo + 2);
                    mma16816(acc[mt][nt2 * 2],     alo[mt], bhi);
                    mma16816(acc[mt][nt2 * 2 + 1], alo[mt], bhi + 2);
                }
            }
        }
    }

    // ---- fused epilogue: /8 + asco + short, mask, softmax over 1024 cols ----
    const int q = lane >> 2, tig = lane & 3;
    const float* ascf = (const float*)(smem_raw + SC_ASCS);
    float* redM = (float*)(smem_raw + SC_REDM);
    float* redS = (float*)(smem_raw + SC_REDS);
    float* redM2 = (float*)(smem_raw + SC_REDM2);
    float* redS2 = (float*)(smem_raw + SC_REDS2);

#pragma unroll
    for (int mt = 0; mt < 2; mt++) {
#pragma unroll
        for (int hf = 0; hf < 2; hf++) {
            int rl = mt * 16 + hf * 8 + q;
            int grow = m0 + rl;
            const float* shp = shortp + ((size_t)bh * S + grow) * S + wid * 64 + tig * 2;
            const int* mkp = mask + ((size_t)b * S + grow) * S + wid * 64 + tig * 2;
            float mx = -1e30f;
#pragma unroll
            for (int nt = 0; nt < 8; nt++) {
                float2 sh = *(const float2*)(shp + nt * 8);
                int2 mk = *(const int2*)(mkp + nt * 8);
                int ci = wid * 64 + nt * 8 + tig * 2;
                float s0 = acc[mt][nt][hf * 2]     * 0.125f + ascf[ci]     + sh.x;
                float s1 = acc[mt][nt][hf * 2 + 1] * 0.125f + ascf[ci + 1] + sh.y;
                s0 = mk.x ? s0 : -1e9f;
                s1 = mk.y ? s1 : -1e9f;
                acc[mt][nt][hf * 2] = s0;
                acc[mt][nt][hf * 2 + 1] = s1;
                mx = fmaxf(mx, fmaxf(s0, s1));
            }
            mx = fmaxf(mx, __shfl_xor_sync(0xffffffffu, mx, 1));
            mx = fmaxf(mx, __shfl_xor_sync(0xffffffffu, mx, 2));
            if (tig == 0) redM[rl * 17 + wid] = mx;
        }
    }
    __syncthreads();
    if (tid < 32) {
        float m = redM[tid * 17];
#pragma unroll
        for (int w = 1; w < 16; w++) m = fmaxf(m, redM[tid * 17 + w]);
        redM2[tid] = m;
    }
    __syncthreads();

#pragma unroll
    for (int mt = 0; mt < 2; mt++) {
#pragma unroll
        for (int hf = 0; hf < 2; hf++) {
            int rl = mt * 16 + hf * 8 + q;
            float m = redM2[rl];
            float sum = 0.f;
#pragma unroll
            for (int nt = 0; nt < 8; nt++) {
                float e0 = __expf(acc[mt][nt][hf * 2] - m);
                float e1 = __expf(acc[mt][nt][hf * 2 + 1] - m);
                acc[mt][nt][hf * 2] = e0;
                acc[mt][nt][hf * 2 + 1] = e1;
                sum += e0 + e1;
            }
            sum += __shfl_xor_sync(0xffffffffu, sum, 1);
            sum += __shfl_xor_sync(0xffffffffu, sum, 2);
            if (tig == 0) redS[rl * 17 + wid] = sum;
        }
    }
    __syncthreads();
    if (tid < 32) {
        float s = 0.f;
#pragma unroll
        for (int w = 0; w < 16; w++) s += redS[tid * 17 + w];
        redS2[tid] = s;
    }
    __syncthreads();

#pragma unroll
    for (int mt = 0; mt < 2; mt++) {
#pragma unroll
        for (int hf = 0; hf < 2; hf++) {
            int rl = mt * 16 + hf * 8 + q;
            int grow = m0 + rl;
            float inv = 1.0f / redS2[rl];
            float* op = out + ((size_t)bh * S + grow) * S + wid * 64 + tig * 2;
#pragma unroll
            for (int nt = 0; nt < 8; nt++) {
                float2 o;
                o.x = acc[mt][nt][hf * 2] * inv;
                o.y = acc[mt][nt][hf * 2 + 1] * inv;
                *(float2*)(op + nt * 8) = o;
            }
        }
    }
}

// ---------------------------------------------------------------------------
extern "C" void kernel_launch(void* const* d_in, const int* in_sizes, int n_in,
                              void* d_out, int out_size)
{
    const float* query  = (const float*)d_in[0];
    const float* key    = (const float*)d_in[1];
    const int*   mask   = (const int*)  d_in[2];
    const float* aspect = (const float*)d_in[3];
    const float* shortp = (const float*)d_in[4];
    const float* Wq     = (const float*)d_in[5];
    const float* bq     = (const float*)d_in[6];
    const float* Wk     = (const float*)d_in[7];
    const float* bk     = (const float*)d_in[8];
    const float* Wd     = (const float*)d_in[9];
    const float* bd     = (const float*)d_in[10];
    const float* wm     = (const float*)d_in[11];
    const float* bm     = (const float*)d_in[12];
    float* out = (float*)d_out;

    cudaFuncSetAttribute(proj_kernel, cudaFuncAttributeMaxDynamicSharedMemorySize, 2 * PJ_BUF);
    cudaFuncSetAttribute(scores_kernel, cudaFuncAttributeMaxDynamicSharedMemorySize, SC_TOTAL);

    // device-pointer handles for __device__ globals
    __nv_bfloat16 *xq_hi, *xq_lo, *xk_hi, *xk_lo, *wq_hi, *wq_lo, *wk_hi, *wk_lo;
    __nv_bfloat16 *q_hi, *q_lo, *k_hi, *k_lo;
    cudaGetSymbolAddress((void**)&xq_hi, g_xq_hi);
    cudaGetSymbolAddress((void**)&xq_lo, g_xq_lo);
    cudaGetSymbolAddress((void**)&xk_hi, g_xk_hi);
    cudaGetSymbolAddress((void**)&xk_lo, g_xk_lo);
    cudaGetSymbolAddress((void**)&wq_hi, g_wq_hi);
    cudaGetSymbolAddress((void**)&wq_lo, g_wq_lo);
    cudaGetSymbolAddress((void**)&wk_hi, g_wk_hi);
    cudaGetSymbolAddress((void**)&wk_lo, g_wk_lo);
    cudaGetSymbolAddress((void**)&q_hi, g_q_hi);
    cudaGetSymbolAddress((void**)&q_lo, g_q_lo);
    cudaGetSymbolAddress((void**)&k_hi, g_k_hi);
    cudaGetSymbolAddress((void**)&k_lo, g_k_lo);

    const int nX4 = BATCH * S * D / 4;     // 1,048,576
    const int nW4 = D * D / 4;             // 262,144
    convert_kernel<<<nX4 / 256, 256>>>(query, xq_hi, xq_lo, nX4);
    convert_kernel<<<nX4 / 256, 256>>>(key, xk_hi, xk_lo, nX4);
    convert_kernel<<<nW4 / 256, 256>>>(Wq, wq_hi, wq_lo, nW4);
    convert_kernel<<<nW4 / 256, 256>>>(Wk, wk_hi, wk_lo, nW4);

    dim3 gp(32, 8);
    proj_kernel<<<gp, 256, 2 * PJ_BUF>>>(xq_hi, xq_lo, wq_hi, wq_lo, bq, q_hi, q_lo);
    proj_kernel<<<gp, 256, 2 * PJ_BUF>>>(xk_hi, xk_lo, wk_hi, wk_lo, bk, k_hi, k_lo);

    aspect_kernel<<<BATCH * H, 256>>>(aspect, Wd, bd, wm, bm);

    dim3 gs(S / 32, H, BATCH);
    scores_kernel<<<gs, 512, SC_TOTAL>>>(shortp, mask, out);
}